// round 11
// baseline (speedup 1.0000x reference)
#include <cuda_runtime.h>
#include <stdint.h>

#define NS      1048576u
#define NTHR    256
#define WPB     8              // warps per block
#define RMAX    64             // P(lane needs >=64 rounds) ~ 1e6*0.5^64 ~ 5e-14 (E[r]~2 measured)
#define MAXBLK  1024

__device__ float g_part[MAXBLK * 10];
__device__ int   g_count = 0;

// JAX threefry2x32 (20 rounds, 5 blocks of 4)
__device__ __forceinline__ void tf(uint32_t k0, uint32_t k1, uint32_t x0, uint32_t x1,
                                   uint32_t& o0, uint32_t& o1) {
    uint32_t ks2 = k0 ^ k1 ^ 0x1BD11BDAu;
    x0 += k0; x1 += k1;
#define R1(r) { x0 += x1; x1 = (x1 << (r)) | (x1 >> (32 - (r))); x1 ^= x0; }
    R1(13) R1(15) R1(26) R1(6)   x0 += k1;  x1 += ks2 + 1u;
    R1(17) R1(29) R1(16) R1(24)  x0 += ks2; x1 += k0  + 2u;
    R1(13) R1(15) R1(26) R1(6)   x0 += k0;  x1 += k1  + 3u;
    R1(17) R1(29) R1(16) R1(24)  x0 += k1;  x1 += ks2 + 4u;
    R1(13) R1(15) R1(26) R1(6)   x0 += ks2; x1 += k0  + 5u;
#undef R1
    o0 = x0; o1 = x1;
}

// ErfInv: XLA Giles polynomial structure, with w from fast MUFU log (validated r7).
__device__ __forceinline__ float erfinv_fast(float x) {
    float om = fmaxf(1.0f - x * x, 1e-38f);
    float w  = -__logf(om);
    float p;
    if (w < 5.0f) {
        float ww = w - 2.5f;
        p = 2.81022636e-08f;
        p = fmaf(p, ww, 3.43273939e-07f);
        p = fmaf(p, ww, -3.5233877e-06f);
        p = fmaf(p, ww, -4.39150654e-06f);
        p = fmaf(p, ww, 0.00021858087f);
        p = fmaf(p, ww, -0.00125372503f);
        p = fmaf(p, ww, -0.00417768164f);
        p = fmaf(p, ww, 0.246640727f);
        p = fmaf(p, ww, 1.50140941f);
    } else {
        float ww = sqrtf(w) - 3.0f;
        p = -0.000200214257f;
        p = fmaf(p, ww, 0.000100950558f);
        p = fmaf(p, ww, 0.00134934322f);
        p = fmaf(p, ww, -0.00367342844f);
        p = fmaf(p, ww, 0.00573950773f);
        p = fmaf(p, ww, -0.0076224613f);
        p = fmaf(p, ww, 0.00943887047f);
        p = fmaf(p, ww, 1.00167406f);
        p = fmaf(p, ww, 2.83297682f);
    }
    return p * x;
}

__device__ __forceinline__ float bits_to_sym_uniform(uint32_t bits) {
    float f  = __uint_as_float((bits >> 9) | 0x3f800000u) - 1.0f;
    float lo = __uint_as_float(0xBF7FFFFFu);
    return fmaxf(lo, fmaf(f, 2.0f, lo));
}

__device__ void rotmat_from_quat(double w, double x, double y, double z, float* r) {
    r[0] = (float)(1.0 - 2.0*(y*y + z*z)); r[1] = (float)(2.0*(x*y - w*z)); r[2] = (float)(2.0*(x*z + w*y));
    r[3] = (float)(2.0*(x*y + w*z)); r[4] = (float)(1.0 - 2.0*(x*x + z*z)); r[5] = (float)(2.0*(y*z - w*x));
    r[6] = (float)(2.0*(x*z - w*y)); r[7] = (float)(2.0*(y*z + w*x)); r[8] = (float)(1.0 - 2.0*(x*x + y*y));
}

struct ParS {
    float q[4]; float Z[3]; float Sig[4]; float lam[4];
};

// One fused kernel: per-block prologue (preamble + key chain), BLOCK-pool warp
// work-stealing sampler (shared cursor), block reduction, last-block finalize.
__global__ void __launch_bounds__(NTHR, 4) fused_kernel(
    const float* __restrict__ zz, const float* __restrict__ zq,
    float* __restrict__ out, int out_size, int lpb)
{
    __shared__ ParS     sp;
    __shared__ uint2    chain[RMAX];
    __shared__ uint4    skeys[RMAX];
    __shared__ float    sh[WPB][10];
    __shared__ int      s_cursor;
    __shared__ int      s_last;

    const int tid  = threadIdx.x;
    const int lane = tid & 31;
    const int wid  = tid >> 5;

    // ---- prologue: thread 0 preamble + serial key chain ----
    if (tid == 0) {
        float cz = 0.f;
        float Z[3];
        for (int i = 0; i < 3; i++) {
            float x  = zz[i];
            float s  = fmaxf(x, 0.f) + log1pf(expf(-fabsf(x)));  // softplus (exact: outputs)
            cz += s;
            Z[i] = -fminf(fmaxf(cz, 1e-12f), 500.f);
        }
        float nq  = sqrtf(zq[0]*zq[0] + zq[1]*zq[1] + zq[2]*zq[2] + zq[3]*zq[3]) + 1e-12f;
        float sgn = ((zq[0] / nq) > 0.f) ? 1.f : -1.f;
        for (int i = 0; i < 4; i++) sp.q[i] = sgn * (zq[i] / nq);
        for (int i = 0; i < 3; i++) sp.Z[i] = Z[i];
        float lam[4] = { 1e-6f, -Z[0], -Z[1], -Z[2] };
        for (int i = 0; i < 4; i++) {
            sp.lam[i] = lam[i];
            sp.Sig[i] = sqrtf(1.0f / fmaf(2.f, lam[i], 1.f));
        }
        uint32_t kh = 0u, kl = 42u;
        for (int r = 0; r < RMAX; r++) {
            chain[r] = make_uint2(kh, kl);
            uint32_t nh, nl;
            tf(kh, kl, 0u, 0u, nh, nl);
            kh = nh; kl = nl;
        }
        s_cursor = NTHR;   // first NTHR pool lanes statically assigned to threads
    }
    __syncthreads();
    if (tid < RMAX) {
        uint32_t kh = chain[tid].x, kl = chain[tid].y;
        uint32_t a, b, c, d;
        tf(kh, kl, 0u, 1u, a, b);   // k1 (normals)
        tf(kh, kl, 0u, 2u, c, d);   // k2 (uniform)
        skeys[tid] = make_uint4(a, b, c, d);
    }
    __syncthreads();

    // ---- sampler: block-pool work stealing ----
    const uint32_t base = (uint32_t)blockIdx.x * (uint32_t)lpb;
    const int pool = (base >= NS) ? 0
                   : ((NS - base < (uint32_t)lpb) ? (int)(NS - base) : lpb);

    float S0 = sp.Sig[0], S1 = sp.Sig[1], S2 = sp.Sig[2], S3 = sp.Sig[3];
    float L0 = sp.lam[0], L1 = sp.lam[1], L2 = sp.lam[2], L3 = sp.lam[3];
    float q0 = sp.q[0],   q1 = sp.q[1],   q2 = sp.q[2],   q3 = sp.q[3];

    float macc[10];
    #pragma unroll
    for (int k = 0; k < 10; k++) macc[k] = 0.f;

    uint32_t my_lane = base + (uint32_t)tid;
    int  r      = 0;
    bool active = (tid < pool);

    while (__ballot_sync(0xffffffffu, active) != 0u) {
        bool accepted = false;
        float y0 = 0.f, y1 = 0.f, y2 = 0.f, y3 = 0.f;
        if (active) {
            uint4 kk = skeys[r];
            uint32_t n4 = my_lane * 4u;

            float eps[4];
            #pragma unroll
            for (int j = 0; j < 4; j++) {
                uint32_t a, b;
                tf(kk.x, kk.y, 0u, n4 + (uint32_t)j, a, b);
                eps[j] = 1.41421356f * erfinv_fast(bits_to_sym_uniform(a ^ b));
            }
            uint32_t a, b;
            tf(kk.z, kk.w, 0u, my_lane, a, b);
            float uu = __uint_as_float(((a ^ b) >> 9) | 0x3f800000u) - 1.0f;

            float yp0 = eps[0] * S0, yp1 = eps[1] * S1, yp2 = eps[2] * S2, yp3 = eps[3] * S3;
            float rs  = rsqrtf(yp0*yp0 + yp1*yp1 + yp2*yp2 + yp3*yp3);
            y0 = yp0 * rs; y1 = yp1 * rs; y2 = yp2 * rs; y3 = yp3 * rs;

            float slam = y0*y0*L0 + y1*y1*L1 + y2*y2*L2 + y3*y3*L3;
            // sinv_i = 1 + 2*lam_i and sum(y^2)=1  =>  sum(y^2 sinv) = 1 + 2*slam
            float sinv = fmaf(2.0f, slam, 1.0f);
            float lr   = fmaf(2.0f, __logf(sinv), -slam - 1.27258873f);

            accepted = (__logf(uu) < lr) || (r == RMAX - 1);
            if (!accepted) r++;
        }
        unsigned fmask = __ballot_sync(0xffffffffu, active && accepted);
        if (fmask) {
            int npop = __popc(fmask);
            int src  = __ffs(fmask) - 1;
            int start0 = 0;
            if (lane == src) start0 = atomicAdd(&s_cursor, npop);
            start0 = __shfl_sync(0xffffffffu, start0, src);

            if (active && accepted) {
                float t0 =  q0*y0 + q1*y1 + q2*y2 + q3*y3;
                float t1 = -q1*y0 + q0*y1 - q3*y2 + q2*y3;
                float t2 = -q2*y0 + q3*y1 + q0*y2 - q1*y3;
                float t3 =  q3*y0 + q2*y1 - q1*y2 - q0*y3;
                float ri = rsqrtf(t0*t0 + t1*t1 + t2*t2 + t3*t3);
                float c0 = t0 * ri, c1 = t1 * ri, c2 = t2 * ri, c3 = t3 * ri;
                macc[0] += c0*c0; macc[1] += c0*c1; macc[2] += c0*c2; macc[3] += c0*c3;
                macc[4] += c1*c1; macc[5] += c1*c2; macc[6] += c1*c3;
                macc[7] += c2*c2; macc[8] += c2*c3; macc[9] += c3*c3;

                int rank = __popc(fmask & ((1u << lane) - 1u));
                int nxt  = start0 + rank;
                if (nxt < pool) { my_lane = base + (uint32_t)nxt; r = 0; }
                else            { active = false; }
            }
        }
    }

    // ---- deterministic-order block reduction ----
    #pragma unroll
    for (int k = 0; k < 10; k++) {
        float v = macc[k];
        #pragma unroll
        for (int off = 16; off; off >>= 1) v += __shfl_down_sync(0xffffffffu, v, off);
        if (lane == 0) sh[wid][k] = v;
    }
    __syncthreads();
    if (tid < 10) {
        float s = 0.f;
        #pragma unroll
        for (int w = 0; w < WPB; w++) s += sh[w][tid];
        g_part[blockIdx.x * 10 + tid] = s;
    }

    // ---- last-block finalize (threadFenceReduction pattern) ----
    __threadfence();
    if (tid == 0) {
        int t = atomicAdd(&g_count, 1);
        s_last = (t == (int)gridDim.x - 1) ? 1 : 0;
    }
    __syncthreads();
    if (!s_last) return;

    __shared__ double sM[10];
    const int nblk = (int)gridDim.x;
    for (int e = wid; e < 10; e += WPB) {
        double s = 0.0;
        for (int b = lane; b < nblk; b += 32) s += (double)g_part[b * 10 + e];
        #pragma unroll
        for (int off = 16; off; off >>= 1)
            s += __shfl_down_sync(0xffffffffu, s, off);
        if (lane == 0) sM[e] = s;
    }
    __syncthreads();

    if (tid != 0) return;
    g_count = 0;   // reset for next graph replay

    double Md[4][4];
    float  A[4][4], Vv[4][4];
    {
        int idx = 0;
        for (int i = 0; i < 4; i++)
            for (int j = i; j < 4; j++) {
                Md[i][j] = sM[idx]; Md[j][i] = sM[idx]; idx++;
            }
    }
    const float inv_ns = 1.0f / (float)NS;
    float fro2 = 0.f;
    for (int i = 0; i < 4; i++)
        for (int j = 0; j < 4; j++) {
            A[i][j]  = (float)Md[i][j] * inv_ns;
            fro2    += A[i][j] * A[i][j];
            Vv[i][j] = (i == j) ? 1.f : 0.f;
        }

    for (int sweep = 0; sweep < 12; sweep++) {
        float off2 = A[0][1]*A[0][1] + A[0][2]*A[0][2] + A[0][3]*A[0][3]
                   + A[1][2]*A[1][2] + A[1][3]*A[1][3] + A[2][3]*A[2][3];
        if (off2 <= 1e-14f * fro2) break;
        for (int p = 0; p < 3; p++)
            for (int q = p + 1; q < 4; q++) {
                float apq = A[p][q];
                if (fabsf(apq) < 1e-30f) continue;
                float theta = (A[q][q] - A[p][p]) / (2.0f * apq);
                float t = ((theta >= 0.f) ? 1.f : -1.f) / (fabsf(theta) + sqrtf(fmaf(theta, theta, 1.f)));
                float c = rsqrtf(fmaf(t, t, 1.f)), s = t * c;
                for (int k = 0; k < 4; k++) {
                    float akp = A[k][p], akq = A[k][q];
                    A[k][p] = c * akp - s * akq;
                    A[k][q] = s * akp + c * akq;
                }
                for (int k = 0; k < 4; k++) {
                    float apk = A[p][k], aqk = A[q][k];
                    A[p][k] = c * apk - s * aqk;
                    A[q][k] = s * apk + c * aqk;
                }
                for (int k = 0; k < 4; k++) {
                    float vkp = Vv[k][p], vkq = Vv[k][q];
                    Vv[k][p] = c * vkp - s * vkq;
                    Vv[k][q] = s * vkp + c * vkq;
                }
            }
    }
    int best = 0;
    for (int i = 1; i < 4; i++) if (A[i][i] > A[best][best]) best = i;
    double v[4] = { (double)Vv[0][best], (double)Vv[1][best],
                    (double)Vv[2][best], (double)Vv[3][best] };

    for (int it = 0; it < 2; it++) {
        double nv[4];
        for (int i = 0; i < 4; i++)
            nv[i] = Md[i][0]*v[0] + Md[i][1]*v[1] + Md[i][2]*v[2] + Md[i][3]*v[3];
        double nn = sqrt(nv[0]*nv[0] + nv[1]*nv[1] + nv[2]*nv[2] + nv[3]*nv[3]);
        double inv = 1.0 / nn;
        for (int i = 0; i < 4; i++) v[i] = nv[i] * inv;
    }
    double e0 = v[0], e1 = v[1], e2 = v[2], e3 = v[3];

    double dq0 = sp.q[0], dq1 = sp.q[1], dq2 = sp.q[2], dq3 = sp.q[3];
    // Sign: reference eigh yields orientation OPPOSITE to analytic mode (verified round 2).
    double d = e0 * dq0 - e1 * dq1 - e2 * dq2 + e3 * dq3;
    if (d > 0.0) { e0 = -e0; e1 = -e1; e2 = -e2; e3 = -e3; }

    float buf[29];
    rotmat_from_quat(e0, e1, e2, e3, buf);
    rotmat_from_quat(dq0, dq1, dq2, dq3, buf + 9);
    buf[18] = (float)dq0; buf[19] = (float)dq1; buf[20] = (float)dq2; buf[21] = (float)dq3;
    buf[22] = sp.Z[0]; buf[23] = sp.Z[1]; buf[24] = sp.Z[2];
    buf[25] = (float)e0; buf[26] = (float)e1; buf[27] = (float)e2; buf[28] = (float)e3;

    int nw = out_size < 29 ? out_size : 29;
    for (int i = 0; i < nw; i++) out[i] = buf[i];
    for (int i = 29; i < out_size; i++) out[i] = 0.f;
}

extern "C" void kernel_launch(void* const* d_in, const int* in_sizes, int n_in,
                              void* d_out, int out_size) {
    const float* zz;
    const float* zq;
    if (in_sizes[0] == 3) { zz = (const float*)d_in[0]; zq = (const float*)d_in[1]; }
    else                  { zq = (const float*)d_in[0]; zz = (const float*)d_in[1]; }

    int dev = 0, sms = 0;
    cudaGetDevice(&dev);
    cudaDeviceGetAttribute(&sms, cudaDevAttrMultiProcessorCount, dev);
    if (sms <= 0) sms = 148;
    int grid = sms * 4;                 // exactly 4 CTAs/SM -> one balanced wave
    if (grid > MAXBLK) grid = MAXBLK;
    int lpb = (int)((NS + (uint32_t)grid - 1u) / (uint32_t)grid);   // lanes per block

    fused_kernel<<<grid, NTHR>>>(zz, zq, (float*)d_out, out_size, lpb);
}

// round 13
// speedup vs baseline: 1.0664x; 1.0664x over previous
#include <cuda_runtime.h>
#include <stdint.h>

#define NS      1048576u
#define NTHR    256
#define WPB     8              // warps per block
#define RMAX    64             // P(lane needs >=64 rounds) ~ 1e6*0.5^64 ~ 5e-14 (E[r]~2 measured)
#define MAXBLK  1024

__device__ float g_part[MAXBLK * 10];
__device__ int   g_count = 0;

// JAX threefry2x32 (20 rounds, 5 blocks of 4)
__device__ __forceinline__ void tf(uint32_t k0, uint32_t k1, uint32_t x0, uint32_t x1,
                                   uint32_t& o0, uint32_t& o1) {
    uint32_t ks2 = k0 ^ k1 ^ 0x1BD11BDAu;
    x0 += k0; x1 += k1;
#define R1(r) { x0 += x1; x1 = (x1 << (r)) | (x1 >> (32 - (r))); x1 ^= x0; }
    R1(13) R1(15) R1(26) R1(6)   x0 += k1;  x1 += ks2 + 1u;
    R1(17) R1(29) R1(16) R1(24)  x0 += ks2; x1 += k0  + 2u;
    R1(13) R1(15) R1(26) R1(6)   x0 += k0;  x1 += k1  + 3u;
    R1(17) R1(29) R1(16) R1(24)  x0 += k1;  x1 += ks2 + 4u;
    R1(13) R1(15) R1(26) R1(6)   x0 += ks2; x1 += k0  + 5u;
#undef R1
    o0 = x0; o1 = x1;
}

__device__ __forceinline__ float bits_to_sym_uniform(uint32_t bits) {
    float f  = __uint_as_float((bits >> 9) | 0x3f800000u) - 1.0f;
    float lo = __uint_as_float(0xBF7FFFFFu);
    return fmaxf(lo, fmaf(f, 2.0f, lo));
}

// Common-branch erfinv polynomial (w < 5); the rare tail is patched separately.
__device__ __forceinline__ float erfinv_common(float w, float x) {
    float ww = w - 2.5f;
    float p = 2.81022636e-08f;
    p = fmaf(p, ww, 3.43273939e-07f);
    p = fmaf(p, ww, -3.5233877e-06f);
    p = fmaf(p, ww, -4.39150654e-06f);
    p = fmaf(p, ww, 0.00021858087f);
    p = fmaf(p, ww, -0.00125372503f);
    p = fmaf(p, ww, -0.00417768164f);
    p = fmaf(p, ww, 0.246640727f);
    p = fmaf(p, ww, 1.50140941f);
    return p * x;
}
__device__ __noinline__ float erfinv_rare(float w, float x) {
    float ww = sqrtf(w) - 3.0f;
    float p = -0.000200214257f;
    p = fmaf(p, ww, 0.000100950558f);
    p = fmaf(p, ww, 0.00134934322f);
    p = fmaf(p, ww, -0.00367342844f);
    p = fmaf(p, ww, 0.00573950773f);
    p = fmaf(p, ww, -0.0076224613f);
    p = fmaf(p, ww, 0.00943887047f);
    p = fmaf(p, ww, 1.00167406f);
    p = fmaf(p, ww, 2.83297682f);
    return p * x;
}

__device__ void rotmat_from_quat(double w, double x, double y, double z, float* r) {
    r[0] = (float)(1.0 - 2.0*(y*y + z*z)); r[1] = (float)(2.0*(x*y - w*z)); r[2] = (float)(2.0*(x*z + w*y));
    r[3] = (float)(2.0*(x*y + w*z)); r[4] = (float)(1.0 - 2.0*(x*x + z*z)); r[5] = (float)(2.0*(y*z - w*x));
    r[6] = (float)(2.0*(x*z - w*y)); r[7] = (float)(2.0*(y*z + w*x)); r[8] = (float)(1.0 - 2.0*(x*x + y*y));
}

struct ParS {
    float q[4]; float Z[3]; float Sig[4]; float lam[4];
};

// Fused kernel: prologue (preamble + key chain), per-warp work-replacement
// sampler with FLAT (predicated) body, block reduction, last-block finalize.
__global__ void __launch_bounds__(NTHR, 4) fused_kernel(
    const float* __restrict__ zz, const float* __restrict__ zq,
    float* __restrict__ out, int out_size, int lpw)
{
    __shared__ ParS     sp;
    __shared__ uint2    chain[RMAX];
    __shared__ uint4    skeys[RMAX];
    __shared__ float    sh[WPB][10];
    __shared__ int      s_last;

    const int tid  = threadIdx.x;
    const int lane = tid & 31;
    const int wid  = tid >> 5;

    // ---- prologue ----
    if (tid == 0) {
        float cz = 0.f;
        float Z[3];
        for (int i = 0; i < 3; i++) {
            float x  = zz[i];
            float s  = fmaxf(x, 0.f) + log1pf(expf(-fabsf(x)));  // softplus (exact: outputs)
            cz += s;
            Z[i] = -fminf(fmaxf(cz, 1e-12f), 500.f);
        }
        float nq  = sqrtf(zq[0]*zq[0] + zq[1]*zq[1] + zq[2]*zq[2] + zq[3]*zq[3]) + 1e-12f;
        float sgn = ((zq[0] / nq) > 0.f) ? 1.f : -1.f;
        for (int i = 0; i < 4; i++) sp.q[i] = sgn * (zq[i] / nq);
        for (int i = 0; i < 3; i++) sp.Z[i] = Z[i];
        float lam[4] = { 1e-6f, -Z[0], -Z[1], -Z[2] };
        for (int i = 0; i < 4; i++) {
            sp.lam[i] = lam[i];
            sp.Sig[i] = sqrtf(1.0f / fmaf(2.f, lam[i], 1.f));
        }
        uint32_t kh = 0u, kl = 42u;
        for (int r = 0; r < RMAX; r++) {
            chain[r] = make_uint2(kh, kl);
            uint32_t nh, nl;
            tf(kh, kl, 0u, 0u, nh, nl);
            kh = nh; kl = nl;
        }
    }
    __syncthreads();
    if (tid < RMAX) {
        uint32_t kh = chain[tid].x, kl = chain[tid].y;
        uint32_t a, b, c, d;
        tf(kh, kl, 0u, 1u, a, b);   // k1 (normals)
        tf(kh, kl, 0u, 2u, c, d);   // k2 (uniform)
        skeys[tid] = make_uint4(a, b, c, d);
    }
    __syncthreads();

    // ---- sampler: per-warp lane pool, flat predicated body ----
    const int warp_g = blockIdx.x * WPB + wid;
    const uint32_t base = (uint32_t)warp_g * (uint32_t)lpw;
    const int pool = (base >= NS) ? 0
                   : ((NS - base < (uint32_t)lpw) ? (int)(NS - base) : lpw);

    float S0 = sp.Sig[0], S1 = sp.Sig[1], S2 = sp.Sig[2], S3 = sp.Sig[3];
    float L0 = sp.lam[0], L1 = sp.lam[1], L2 = sp.lam[2], L3 = sp.lam[3];
    float q0 = sp.q[0],   q1 = sp.q[1],   q2 = sp.q[2],   q3 = sp.q[3];

    float macc[10];
    #pragma unroll
    for (int k = 0; k < 10; k++) macc[k] = 0.f;

    uint32_t my_lane = base + (uint32_t)lane;
    int  r      = 0;
    int  cursor = 32;               // warp-uniform
    bool active = (lane < pool);

    while (__ballot_sync(0xffffffffu, active) != 0u) {
        // proposal (computed by every lane; inactive lanes redo stale data harmlessly)
        uint4 kk = skeys[r];
        uint32_t n4 = my_lane * 4u;

        float x[4], w[4];
        bool rare = false;
        #pragma unroll
        for (int j = 0; j < 4; j++) {
            uint32_t a, b;
            tf(kk.x, kk.y, 0u, n4 + (uint32_t)j, a, b);
            x[j] = bits_to_sym_uniform(a ^ b);
            float om = fmaxf(1.0f - x[j] * x[j], 1e-38f);
            w[j] = -__logf(om);
            rare = rare || (w[j] >= 5.0f);
        }
        float eps[4];
        #pragma unroll
        for (int j = 0; j < 4; j++)
            eps[j] = 1.41421356f * erfinv_common(w[j], x[j]);
        if (__any_sync(0xffffffffu, rare)) {     // ~0.3%/draw tail, one uniform branch
            #pragma unroll
            for (int j = 0; j < 4; j++)
                if (w[j] >= 5.0f) eps[j] = 1.41421356f * erfinv_rare(w[j], x[j]);
        }

        uint32_t ua, ub;
        tf(kk.z, kk.w, 0u, my_lane, ua, ub);
        float uu = __uint_as_float(((ua ^ ub) >> 9) | 0x3f800000u) - 1.0f;

        float yp0 = eps[0] * S0, yp1 = eps[1] * S1, yp2 = eps[2] * S2, yp3 = eps[3] * S3;
        float rs  = rsqrtf(yp0*yp0 + yp1*yp1 + yp2*yp2 + yp3*yp3);
        float y0 = yp0 * rs, y1 = yp1 * rs, y2 = yp2 * rs, y3 = yp3 * rs;

        float slam = y0*y0*L0 + y1*y1*L1 + y2*y2*L2 + y3*y3*L3;
        float sinv = fmaf(2.0f, slam, 1.0f);     // sum(y^2 sinv) = 1 + 2*slam (validated r10)
        float lr   = fmaf(2.0f, __logf(sinv), -slam - 1.27258873f);

        bool accepted = active && ((__logf(uu) < lr) || (r == RMAX - 1));
        r = accepted ? 0 : ((r < RMAX - 1) ? r + 1 : r);

        unsigned fmask = __ballot_sync(0xffffffffu, accepted);

        // accept-side, fully predicated (adds +0 for non-accepting lanes)
        float t0 =  q0*y0 + q1*y1 + q2*y2 + q3*y3;
        float t1 = -q1*y0 + q0*y1 - q3*y2 + q2*y3;
        float t2 = -q2*y0 + q3*y1 + q0*y2 - q1*y3;
        float t3 =  q3*y0 + q2*y1 - q1*y2 - q0*y3;
        float dot = t0*t0 + t1*t1 + t2*t2 + t3*t3;
        float ri  = accepted ? rsqrtf(dot) : 0.0f;
        float c0 = t0 * ri, c1 = t1 * ri, c2 = t2 * ri, c3 = t3 * ri;
        macc[0] += c0*c0; macc[1] += c0*c1; macc[2] += c0*c2; macc[3] += c0*c3;
        macc[4] += c1*c1; macc[5] += c1*c2; macc[6] += c1*c3;
        macc[7] += c2*c2; macc[8] += c2*c3; macc[9] += c3*c3;

        // work replacement, predicated
        int rank = __popc(fmask & ((1u << lane) - 1u));
        int nxt  = cursor + rank;
        bool take = accepted && (nxt < pool);
        my_lane = take ? base + (uint32_t)nxt : my_lane;
        r       = take ? 0 : r;
        active  = active && (!accepted || take);
        cursor += __popc(fmask);
    }

    // ---- deterministic-order block reduction ----
    #pragma unroll
    for (int k = 0; k < 10; k++) {
        float v = macc[k];
        #pragma unroll
        for (int off = 16; off; off >>= 1) v += __shfl_down_sync(0xffffffffu, v, off);
        if (lane == 0) sh[wid][k] = v;
    }
    __syncthreads();
    if (tid < 10) {
        float s = 0.f;
        #pragma unroll
        for (int w2 = 0; w2 < WPB; w2++) s += sh[w2][tid];
        g_part[blockIdx.x * 10 + tid] = s;
    }

    // ---- last-block finalize ----
    __threadfence();
    if (tid == 0) {
        int t = atomicAdd(&g_count, 1);
        s_last = (t == (int)gridDim.x - 1) ? 1 : 0;
    }
    __syncthreads();
    if (!s_last) return;

    __shared__ double sM[10];
    const int nblk = (int)gridDim.x;
    for (int e = wid; e < 10; e += WPB) {
        double s = 0.0;
        for (int b = lane; b < nblk; b += 32) s += (double)g_part[b * 10 + e];
        #pragma unroll
        for (int off = 16; off; off >>= 1)
            s += __shfl_down_sync(0xffffffffu, s, off);
        if (lane == 0) sM[e] = s;
    }
    __syncthreads();

    if (tid != 0) return;
    g_count = 0;   // reset for next graph replay

    double Md[4][4];
    float  A[4][4], Vv[4][4];
    {
        int idx = 0;
        for (int i = 0; i < 4; i++)
            for (int j = i; j < 4; j++) {
                Md[i][j] = sM[idx]; Md[j][i] = sM[idx]; idx++;
            }
    }
    const float inv_ns = 1.0f / (float)NS;
    float fro2 = 0.f;
    for (int i = 0; i < 4; i++)
        for (int j = 0; j < 4; j++) {
            A[i][j]  = (float)Md[i][j] * inv_ns;
            fro2    += A[i][j] * A[i][j];
            Vv[i][j] = (i == j) ? 1.f : 0.f;
        }

    for (int sweep = 0; sweep < 12; sweep++) {
        float off2 = A[0][1]*A[0][1] + A[0][2]*A[0][2] + A[0][3]*A[0][3]
                   + A[1][2]*A[1][2] + A[1][3]*A[1][3] + A[2][3]*A[2][3];
        if (off2 <= 1e-14f * fro2) break;
        for (int p = 0; p < 3; p++)
            for (int q = p + 1; q < 4; q++) {
                float apq = A[p][q];
                if (fabsf(apq) < 1e-30f) continue;
                float theta = (A[q][q] - A[p][p]) / (2.0f * apq);
                float t = ((theta >= 0.f) ? 1.f : -1.f) / (fabsf(theta) + sqrtf(fmaf(theta, theta, 1.f)));
                float c = rsqrtf(fmaf(t, t, 1.f)), s = t * c;
                for (int k = 0; k < 4; k++) {
                    float akp = A[k][p], akq = A[k][q];
                    A[k][p] = c * akp - s * akq;
                    A[k][q] = s * akp + c * akq;
                }
                for (int k = 0; k < 4; k++) {
                    float apk = A[p][k], aqk = A[q][k];
                    A[p][k] = c * apk - s * aqk;
                    A[q][k] = s * apk + c * aqk;
                }
                for (int k = 0; k < 4; k++) {
                    float vkp = Vv[k][p], vkq = Vv[k][q];
                    Vv[k][p] = c * vkp - s * vkq;
                    Vv[k][q] = s * vkp + c * vkq;
                }
            }
    }
    int best = 0;
    for (int i = 1; i < 4; i++) if (A[i][i] > A[best][best]) best = i;
    double v[4] = { (double)Vv[0][best], (double)Vv[1][best],
                    (double)Vv[2][best], (double)Vv[3][best] };

    for (int it = 0; it < 2; it++) {
        double nv[4];
        for (int i = 0; i < 4; i++)
            nv[i] = Md[i][0]*v[0] + Md[i][1]*v[1] + Md[i][2]*v[2] + Md[i][3]*v[3];
        double nn = sqrt(nv[0]*nv[0] + nv[1]*nv[1] + nv[2]*nv[2] + nv[3]*nv[3]);
        double inv = 1.0 / nn;
        for (int i = 0; i < 4; i++) v[i] = nv[i] * inv;
    }
    double e0 = v[0], e1 = v[1], e2 = v[2], e3 = v[3];

    double dq0 = sp.q[0], dq1 = sp.q[1], dq2 = sp.q[2], dq3 = sp.q[3];
    // Sign: reference eigh yields orientation OPPOSITE to analytic mode (verified round 2).
    double d = e0 * dq0 - e1 * dq1 - e2 * dq2 + e3 * dq3;
    if (d > 0.0) { e0 = -e0; e1 = -e1; e2 = -e2; e3 = -e3; }

    float buf[29];
    rotmat_from_quat(e0, e1, e2, e3, buf);
    rotmat_from_quat(dq0, dq1, dq2, dq3, buf + 9);
    buf[18] = (float)dq0; buf[19] = (float)dq1; buf[20] = (float)dq2; buf[21] = (float)dq3;
    buf[22] = sp.Z[0]; buf[23] = sp.Z[1]; buf[24] = sp.Z[2];
    buf[25] = (float)e0; buf[26] = (float)e1; buf[27] = (float)e2; buf[28] = (float)e3;

    int nw = out_size < 29 ? out_size : 29;
    for (int i = 0; i < nw; i++) out[i] = buf[i];
    for (int i = 29; i < out_size; i++) out[i] = 0.f;
}

extern "C" void kernel_launch(void* const* d_in, const int* in_sizes, int n_in,
                              void* d_out, int out_size) {
    const float* zz;
    const float* zq;
    if (in_sizes[0] == 3) { zz = (const float*)d_in[0]; zq = (const float*)d_in[1]; }
    else                  { zq = (const float*)d_in[0]; zz = (const float*)d_in[1]; }

    int dev = 0, sms = 0;
    cudaGetDevice(&dev);
    cudaDeviceGetAttribute(&sms, cudaDevAttrMultiProcessorCount, dev);
    if (sms <= 0) sms = 148;
    int grid = sms * 4;                 // exactly 4 CTAs/SM -> one balanced wave
    if (grid > MAXBLK) grid = MAXBLK;
    int warps = grid * WPB;
    int lpw   = (int)((NS + (uint32_t)warps - 1u) / (uint32_t)warps);

    fused_kernel<<<grid, NTHR>>>(zz, zq, (float*)d_out, out_size, lpw);
}